// round 1
// baseline (speedup 1.0000x reference)
#include <cuda_runtime.h>
#include <math.h>

#define BB 16
#define NN 8192
#define CC 128
#define NC (NN*CC)          // 1048576
#define BNC (BB*NC)         // 16777216

// ---------------- scratch (device globals; no dynamic allocation) ----------
__device__ float  g_mean[4][NC];       // 0:hf_shared 1:hf_private 2:lf_shared 3:lf_private
__device__ float  g_G[2][BB][CC*CC];   // Gram partials  (2 MB)
__device__ float  g_n2[2][2][BB][CC];  // [pair][0=x/1=s][b][c] centered sum-of-squares
__device__ int    g_ord[2][NN];        // descending-stable argsort of gt_rank rows 0,1
__device__ int    g_cnt[2];            // count(gt_rank[b] > 0)
__device__ double g_acc[8];            // 0 pearson, 1 sep, 2 cost, 3 recon_hf, 4 recon_lf

// ---------------- helpers ---------------------------------------------------
__device__ __forceinline__ float wredf(float v) {
    #pragma unroll
    for (int o = 16; o; o >>= 1) v += __shfl_down_sync(0xffffffffu, v, o);
    return v;
}

__device__ __forceinline__ void block_add(double v, double* target) {
    __shared__ double sd[8];
    #pragma unroll
    for (int o = 16; o; o >>= 1) v += __shfl_down_sync(0xffffffffu, v, o);
    int lane = threadIdx.x & 31, w = threadIdx.x >> 5;
    if (lane == 0) sd[w] = v;
    __syncthreads();
    if (threadIdx.x == 0) {
        double s = 0;
        int nw = blockDim.x >> 5;
        for (int i = 0; i < nw; i++) s += sd[i];
        atomicAdd(target, s);
    }
}

// ---------------- kernels ---------------------------------------------------

// zero accumulators: g_G (524288 f) + g_n2 (8192 f) + g_acc + g_cnt
__global__ void k_init() {
    int i = blockIdx.x * 256 + threadIdx.x;
    if (i < 2*BB*CC*CC) ((float*)g_G)[i] = 0.f;
    else {
        int j = i - 2*BB*CC*CC;
        if (j < 2*2*BB*CC) ((float*)g_n2)[j] = 0.f;
    }
    if (i < 8) g_acc[i] = 0.0;
    if (i < 2) g_cnt[i] = 0;
}

// batch-means of the 4 shared/private tensors: mean over b for each (n,c)
__global__ void k_mean(const float* __restrict__ a, const float* __restrict__ b,
                       const float* __restrict__ c, const float* __restrict__ d) {
    int idx = blockIdx.x * 256 + threadIdx.x;       // 0..NC-1
    const float* src; float* dst;
    switch (blockIdx.y) {
        case 0:  src = a; dst = g_mean[0]; break;
        case 1:  src = b; dst = g_mean[1]; break;
        case 2:  src = c; dst = g_mean[2]; break;
        default: src = d; dst = g_mean[3]; break;
    }
    float s = 0.f;
    #pragma unroll
    for (int bb = 0; bb < BB; bb++) s += src[(size_t)bb * NC + idx];
    dst[idx] = s * 0.0625f;
}

// split-K SGEMM: G[pair][b] += Xc^T * Sc over a 512-node chunk; fuses centering
// and the per-column centered sum-of-squares (for the norms).
__global__ __launch_bounds__(256, 2)
void k_gemm(const float* __restrict__ hf_s, const float* __restrict__ hf_p,
            const float* __restrict__ lf_s, const float* __restrict__ lf_p) {
    int pair = blockIdx.z;
    const float* X  = pair ? lf_s : hf_s;
    const float* S  = pair ? lf_p : hf_p;
    const float* mX = pair ? g_mean[2] : g_mean[0];
    const float* mS = pair ? g_mean[3] : g_mean[1];
    int b = blockIdx.y;
    int k0base = blockIdx.x * 512;

    __shared__ float Xs[16][128];
    __shared__ float Ss[16][128];

    int t  = threadIdx.x;
    int c  = t & 127, r2 = t >> 7;     // loader mapping
    int tx = t & 15,  ty = t >> 4;     // 16x16 compute grid, 8x8 microtile

    float acc[8][8];
    #pragma unroll
    for (int i = 0; i < 8; i++)
        #pragma unroll
        for (int j = 0; j < 8; j++) acc[i][j] = 0.f;

    float sqx = 0.f, sqs = 0.f;
    const float* Xb = X + (size_t)b * NC;
    const float* Sb = S + (size_t)b * NC;

    for (int k0 = k0base; k0 < k0base + 512; k0 += 16) {
        #pragma unroll
        for (int i = 0; i < 8; i++) {
            int row = r2 + 2 * i;
            int gi = (k0 + row) * CC + c;
            float xv = Xb[gi] - mX[gi];
            float sv = Sb[gi] - mS[gi];
            Xs[row][c] = xv;  Ss[row][c] = sv;
            sqx += xv * xv;   sqs += sv * sv;
        }
        __syncthreads();
        #pragma unroll
        for (int kk = 0; kk < 16; kk++) {
            float av[8], bv[8];
            *(float4*)(av)     = *(const float4*)&Xs[kk][ty * 8];
            *(float4*)(av + 4) = *(const float4*)&Xs[kk][ty * 8 + 4];
            *(float4*)(bv)     = *(const float4*)&Ss[kk][tx * 8];
            *(float4*)(bv + 4) = *(const float4*)&Ss[kk][tx * 8 + 4];
            #pragma unroll
            for (int i = 0; i < 8; i++)
                #pragma unroll
                for (int j = 0; j < 8; j++)
                    acc[i][j] += av[i] * bv[j];
        }
        __syncthreads();
    }

    float* Gp = g_G[pair][b];
    #pragma unroll
    for (int i = 0; i < 8; i++)
        #pragma unroll
        for (int j = 0; j < 8; j++)
            atomicAdd(&Gp[(ty * 8 + i) * CC + tx * 8 + j], acc[i][j]);
    atomicAdd(&g_n2[pair][0][b][c], sqx);
    atomicAdd(&g_n2[pair][1][b][c], sqs);
}

// reconstruction MSE sums (both pairs)
__global__ void k_recon(const float* __restrict__ r_hf, const float* __restrict__ hf,
                        const float* __restrict__ r_lf, const float* __restrict__ lf) {
    int pair = blockIdx.y;
    const float* r = pair ? r_lf : r_hf;
    const float* o = pair ? lf   : hf;
    float local = 0.f;
    int stride = gridDim.x * blockDim.x;
    for (int i = blockIdx.x * blockDim.x + threadIdx.x; i < BNC; i += stride) {
        float d = r[i] - o[i];
        local += d * d;
    }
    block_add((double)local, &g_acc[3 + pair]);
}

// stable descending argsort rank (count-based) + positives count, rows 0 and 1
__global__ void k_rank(const float* __restrict__ gt) {
    __shared__ float row[NN];
    int batch = blockIdx.y;
    const float* gr = gt + batch * NN;
    for (int j = threadIdx.x; j < NN; j += 128) row[j] = gr[j];
    __syncthreads();

    int i = blockIdx.x * 128 + threadIdx.x;
    float xi = row[i];
    int cgt = 0, ceq = 0;
    for (int j = 0; j < NN; j += 4) {
        float4 v = *(const float4*)&row[j];
        cgt += (v.x > xi) + (v.y > xi) + (v.z > xi) + (v.w > xi);
        ceq += (v.x == xi && j     < i);
        ceq += (v.y == xi && j + 1 < i);
        ceq += (v.z == xi && j + 2 < i);
        ceq += (v.w == xi && j + 3 < i);
    }
    g_ord[batch][cgt + ceq] = i;

    int pos = (xi > 0.f) ? 1 : 0;
    #pragma unroll
    for (int o = 16; o; o >>= 1) pos += __shfl_down_sync(0xffffffffu, pos, o);
    __shared__ int ws[4];
    if ((threadIdx.x & 31) == 0) ws[threadIdx.x >> 5] = pos;
    __syncthreads();
    if (threadIdx.x == 0) atomicAdd(&g_cnt[batch], ws[0] + ws[1] + ws[2] + ws[3]);
}

// masked cosine-embedding sum over sorted pairs (one warp per sorted position)
__global__ void k_sepcos(const float* __restrict__ sep) {
    int w = threadIdx.x >> 5, lane = threadIdx.x & 31;
    int p = blockIdx.x * 8 + w;
    int i0 = g_ord[0][p], i1 = g_ord[1][p];
    const float4* r0 = (const float4*)(sep + (size_t)i0 * CC);
    const float4* r1 = (const float4*)(sep + (size_t)NC + (size_t)i1 * CC);
    float4 a = r0[lane], b = r1[lane];
    float dot = a.x*b.x + a.y*b.y + a.z*b.z + a.w*b.w;
    float nx  = a.x*a.x + a.y*a.y + a.z*a.z + a.w*a.w;
    float ny  = b.x*b.x + b.y*b.y + b.z*b.z + b.w*b.w;
    dot = wredf(dot); nx = wredf(nx); ny = wredf(ny);

    __shared__ double part[8];
    if (lane == 0) {
        int s0 = g_cnt[0]; if (s0 == 0) s0 = NN;
        int s1 = g_cnt[1]; if (s1 == 0) s1 = NN;
        int index = min(s0, s1);
        float cs = dot / (fmaxf(sqrtf(nx), 1e-8f) * fmaxf(sqrtf(ny), 1e-8f));
        part[w] = (p < index) ? (double)(1.f - cs) : 0.0;
    }
    __syncthreads();
    if (threadIdx.x == 0) {
        double s = 0;
        #pragma unroll
        for (int k = 0; k < 8; k++) s += part[k];
        atomicAdd(&g_acc[1], s);
    }
}

// pearson over first 16 rows of flattened [B*N, C] (= batch0 nodes 0..15)
__global__ void k_pear(const float* __restrict__ x, const float* __restrict__ y) {
    int w = threadIdx.x >> 5, lane = threadIdx.x & 31;   // w = row 0..15
    const float4* xr = (const float4*)(x + w * CC);
    const float4* yr = (const float4*)(y + w * CC);
    float4 a = xr[lane], b = yr[lane];
    float sx  = a.x + a.y + a.z + a.w;
    float sy  = b.x + b.y + b.z + b.w;
    float sxx = a.x*a.x + a.y*a.y + a.z*a.z + a.w*a.w;
    float syy = b.x*b.x + b.y*b.y + b.z*b.z + b.w*b.w;
    float sxy = a.x*b.x + a.y*b.y + a.z*b.z + a.w*b.w;
    sx = wredf(sx); sy = wredf(sy); sxx = wredf(sxx); syy = wredf(syy); sxy = wredf(sxy);
    if (lane == 0) {
        double n = 128.0;
        double num = (double)sxy - (double)sx * (double)sy / n;
        double d2  = ((double)sxx - (double)sx * (double)sx / n) *
                     ((double)syy - (double)sy * (double)sy / n);
        double den = sqrt(d2);
        double r   = (den == 0.0) ? 0.0 : num / den;
        atomicAdd(&g_acc[0], 1.0 - r);
    }
}

// sum of squared normalized correlations over both pairs
__global__ void k_cost() {
    int idx  = blockIdx.x * 256 + threadIdx.x;      // 0 .. 2*BB*CC*CC-1
    int pair = idx >> 18;
    int rem  = idx & (BB*CC*CC - 1);
    int b    = rem >> 14;
    int cd   = rem & (CC*CC - 1);
    int c    = cd >> 7;
    int d    = cd & (CC - 1);
    float g  = g_G[pair][b][cd];
    float nx = fmaxf(sqrtf(g_n2[pair][0][b][c]), 1e-12f);
    float ns = fmaxf(sqrtf(g_n2[pair][1][b][d]), 1e-12f);
    float v  = g / (nx * ns);
    block_add((double)(v * v), &g_acc[2]);
}

// final scalar assembly
__global__ void k_final(float* __restrict__ out) {
    double sim   = g_acc[0] / 16.0;
    double cost  = g_acc[2] / (double)(BB * CC * CC);   // diff2 + diff3 (both >= 0)
    double recon = (g_acc[3] + g_acc[4]) / (double)BNC;
    int s0 = g_cnt[0]; if (s0 == 0) s0 = NN;
    int s1 = g_cnt[1]; if (s1 == 0) s1 = NN;
    int index = min(s0, s1);
    double gnn = g_acc[1] / (double)index;
    out[0] = (float)(2.0 * sim + 1.0 * cost + 0.05 * recon + gnn);
}

// ---------------- launch ----------------------------------------------------
extern "C" void kernel_launch(void* const* d_in, const int* in_sizes, int n_in,
                              void* d_out, int out_size) {
    const float* hf_f = (const float*)d_in[0];
    const float* lf_f = (const float*)d_in[1];
    const float* hf_s = (const float*)d_in[2];
    const float* lf_s = (const float*)d_in[3];
    const float* hf_p = (const float*)d_in[4];
    const float* lf_p = (const float*)d_in[5];
    const float* r_hf = (const float*)d_in[6];
    const float* r_lf = (const float*)d_in[7];
    const float* sep  = (const float*)d_in[8];
    /* d_in[9] = noi_node: contributes exactly zero (diff_loss on batch-of-1) */
    const float* gt   = (const float*)d_in[10];
    float* out = (float*)d_out;

    k_init  <<<2080, 256>>>();
    k_mean  <<<dim3(NC/256, 4), 256>>>(hf_s, hf_p, lf_s, lf_p);
    k_rank  <<<dim3(64, 2), 128>>>(gt);
    k_recon <<<dim3(2048, 2), 256>>>(r_hf, hf_f, r_lf, lf_f);
    k_gemm  <<<dim3(16, 16, 2), 256>>>(hf_s, hf_p, lf_s, lf_p);
    k_sepcos<<<1024, 256>>>(sep);
    k_pear  <<<1, 512>>>(hf_s, lf_s);
    k_cost  <<<2048, 256>>>();
    k_final <<<1, 1>>>(out);
}

// round 7
// speedup vs baseline: 1.6750x; 1.6750x over previous
#include <cuda_runtime.h>
#include <cuda_bf16.h>
#include <stdint.h>
#include <cstdint>
#include <math.h>

#define BB 16
#define NN 8192
#define CC 128
#define NC (NN*CC)          // 1048576
#define BNC (BB*NC)         // 16777216

// ---------------- scratch (device globals; no dynamic allocation) ----------
__device__ float  g_mean[4][NC];       // 0:hf_shared 1:hf_private 2:lf_shared 3:lf_private
__device__ float  g_G[2][BB][CC*CC];   // Gram partials  (2 MB)
__device__ float  g_n2[2][2][BB][CC];  // [pair][0=x/1=s][b][c] centered sum-of-squares
__device__ int    g_ord[2][NN];        // descending-stable argsort of gt_rank rows 0,1
__device__ int    g_cnt[2];            // count(gt_rank[b] > 0)
__device__ double g_acc[8];            // 0 pearson, 1 sep, 2 cost, 3 recon_hf, 4 recon_lf

// ---------------- helpers ---------------------------------------------------
__device__ __forceinline__ float wredf(float v) {
    #pragma unroll
    for (int o = 16; o; o >>= 1) v += __shfl_down_sync(0xffffffffu, v, o);
    return v;
}

__device__ __forceinline__ void block_add(double v, double* target) {
    __shared__ double sd[8];
    #pragma unroll
    for (int o = 16; o; o >>= 1) v += __shfl_down_sync(0xffffffffu, v, o);
    int lane = threadIdx.x & 31, w = threadIdx.x >> 5;
    if (lane == 0) sd[w] = v;
    __syncthreads();
    if (threadIdx.x == 0) {
        double s = 0;
        int nw = blockDim.x >> 5;
        for (int i = 0; i < nw; i++) s += sd[i];
        atomicAdd(target, s);
    }
}

// PTX wrappers (scalar-reference pattern — matches ptx_helpers.cuh style)
__device__ __forceinline__ void ldsm_x4_t(uint32_t& r0, uint32_t& r1,
                                          uint32_t& r2, uint32_t& r3, uint32_t addr) {
    asm volatile("ldmatrix.sync.aligned.m8n8.x4.trans.shared.b16 {%0,%1,%2,%3}, [%4];"
        : "=r"(r0), "=r"(r1), "=r"(r2), "=r"(r3) : "r"(addr));
}

__device__ __forceinline__ void mma_bf16_16816(float& c0, float& c1, float& c2, float& c3,
                                               uint32_t a0, uint32_t a1, uint32_t a2, uint32_t a3,
                                               uint32_t b0, uint32_t b1) {
    asm volatile(
        "mma.sync.aligned.m16n8k16.row.col.f32.bf16.bf16.f32 "
        "{%0,%1,%2,%3}, {%4,%5,%6,%7}, {%8,%9}, {%0,%1,%2,%3};"
        : "+f"(c0), "+f"(c1), "+f"(c2), "+f"(c3)
        : "r"(a0), "r"(a1), "r"(a2), "r"(a3), "r"(b0), "r"(b1));
}

// ---------------- kernels ---------------------------------------------------

__global__ void k_init() {
    int i = blockIdx.x * 256 + threadIdx.x;
    if (i < 2*BB*CC*CC) ((float*)g_G)[i] = 0.f;
    else {
        int j = i - 2*BB*CC*CC;
        if (j < 2*2*BB*CC) ((float*)g_n2)[j] = 0.f;
    }
    if (i < 8) g_acc[i] = 0.0;
    if (i < 2) g_cnt[i] = 0;
}

// batch-means of the 4 shared/private tensors (float4 vectorized)
__global__ void k_mean(const float* __restrict__ a, const float* __restrict__ b,
                       const float* __restrict__ c, const float* __restrict__ d) {
    int idx = blockIdx.x * 256 + threadIdx.x;       // float4 index 0..NC/4-1
    const float4* src; float4* dst;
    switch (blockIdx.y) {
        case 0:  src = (const float4*)a; dst = (float4*)g_mean[0]; break;
        case 1:  src = (const float4*)b; dst = (float4*)g_mean[1]; break;
        case 2:  src = (const float4*)c; dst = (float4*)g_mean[2]; break;
        default: src = (const float4*)d; dst = (float4*)g_mean[3]; break;
    }
    float4 s = make_float4(0.f, 0.f, 0.f, 0.f);
    #pragma unroll
    for (int bb = 0; bb < BB; bb++) {
        float4 v = src[(size_t)bb * (NC/4) + idx];
        s.x += v.x; s.y += v.y; s.z += v.z; s.w += v.w;
    }
    s.x *= 0.0625f; s.y *= 0.0625f; s.z *= 0.0625f; s.w *= 0.0625f;
    dst[idx] = s;
}

// ---- tensor-core split-K Gram: G[pair][b] += Xc^T * Sc (bf16 mma, fp32 acc)
// SMEM tile: [32 k-rows][128 cols] bf16, 256B rows, 16B-chunk XOR swizzle.
__device__ __forceinline__ uint32_t swz(int row, int cbyte) {
    return (uint32_t)(row * 256 + (cbyte ^ ((row & 7) << 4)));
}

__global__ __launch_bounds__(256, 2)
void k_gemm(const float* __restrict__ hf_s, const float* __restrict__ hf_p,
            const float* __restrict__ lf_s, const float* __restrict__ lf_p) {
    __shared__ __align__(16) unsigned char smem[16384];   // X: [0,8K), S: [8K,16K)

    int pair = blockIdx.z, b = blockIdx.y;
    const float* X  = pair ? lf_s : hf_s;
    const float* S  = pair ? lf_p : hf_p;
    const float* mX = pair ? g_mean[2] : g_mean[0];
    const float* mS = pair ? g_mean[3] : g_mean[1];
    const float* Xb = X + (size_t)b * NC;
    const float* Sb = S + (size_t)b * NC;

    int t = threadIdx.x;
    int lane = t & 31, warp = t >> 5;
    int wm = (warp >> 2) * 64;          // warp m-origin (c-dim of X)
    int wn = (warp & 3) * 32;           // warp n-origin (c-dim of S)

    uint32_t sbase = (uint32_t)__cvta_generic_to_shared(smem);
    uint32_t sX = sbase, sS = sbase + 8192;

    // loader mapping: 32 lanes cover 128 cols as float4; 8 row-groups
    int lc = lane * 4;
    int lr = warp;

    // ldmatrix.x4.trans lane address pieces
    int a_r = ((lane >> 4) & 1) * 8 + (lane & 7);
    int a_c = ((lane >> 3) & 1) * 8;
    int b_r = ((lane >> 3) & 1) * 8 + (lane & 7);
    int b_c = ((lane >> 4) & 1) * 8;

    float acc[4][16];
    #pragma unroll
    for (int i = 0; i < 4; i++)
        #pragma unroll
        for (int j = 0; j < 16; j++) acc[i][j] = 0.f;

    float4 sqx = make_float4(0.f,0.f,0.f,0.f), sqs = make_float4(0.f,0.f,0.f,0.f);

    int kbase = blockIdx.x * 1024;
    for (int st = 0; st < 32; st++) {
        int k0 = kbase + st * 32;
        #pragma unroll
        for (int p = 0; p < 4; p++) {
            int row = lr + 8 * p;
            int gi = (k0 + row) * CC + lc;
            float4 xv = *(const float4*)&Xb[gi];
            float4 mx = *(const float4*)&mX[gi];
            float4 sv = *(const float4*)&Sb[gi];
            float4 ms = *(const float4*)&mS[gi];
            xv.x -= mx.x; xv.y -= mx.y; xv.z -= mx.z; xv.w -= mx.w;
            sv.x -= ms.x; sv.y -= ms.y; sv.z -= ms.z; sv.w -= ms.w;
            sqx.x += xv.x*xv.x; sqx.y += xv.y*xv.y; sqx.z += xv.z*xv.z; sqx.w += xv.w*xv.w;
            sqs.x += sv.x*sv.x; sqs.y += sv.y*sv.y; sqs.z += sv.z*sv.z; sqs.w += sv.w*sv.w;
            __nv_bfloat162 x01 = __floats2bfloat162_rn(xv.x, xv.y);
            __nv_bfloat162 x23 = __floats2bfloat162_rn(xv.z, xv.w);
            __nv_bfloat162 s01 = __floats2bfloat162_rn(sv.x, sv.y);
            __nv_bfloat162 s23 = __floats2bfloat162_rn(sv.z, sv.w);
            uint32_t ad = swz(row, lc * 2);
            *(uint2*)(smem + ad)        = make_uint2(*(uint32_t*)&x01, *(uint32_t*)&x23);
            *(uint2*)(smem + 8192 + ad) = make_uint2(*(uint32_t*)&s01, *(uint32_t*)&s23);
        }
        __syncthreads();

        #pragma unroll
        for (int kk = 0; kk < 32; kk += 16) {
            uint32_t A0[4], A1[4], A2[4], A3[4];
            uint32_t B0[4], B1[4];
            int ra = kk + a_r;
            ldsm_x4_t(A0[0], A0[1], A0[2], A0[3], sX + swz(ra, (wm      + a_c) * 2));
            ldsm_x4_t(A1[0], A1[1], A1[2], A1[3], sX + swz(ra, (wm + 16 + a_c) * 2));
            ldsm_x4_t(A2[0], A2[1], A2[2], A2[3], sX + swz(ra, (wm + 32 + a_c) * 2));
            ldsm_x4_t(A3[0], A3[1], A3[2], A3[3], sX + swz(ra, (wm + 48 + a_c) * 2));
            int rb = kk + b_r;
            ldsm_x4_t(B0[0], B0[1], B0[2], B0[3], sS + swz(rb, (wn      + b_c) * 2));
            ldsm_x4_t(B1[0], B1[1], B1[2], B1[3], sS + swz(rb, (wn + 16 + b_c) * 2));
            #pragma unroll
            for (int i = 0; i < 4; i++) {
                uint32_t* Ai = (i == 0) ? A0 : (i == 1) ? A1 : (i == 2) ? A2 : A3;
                mma_bf16_16816(acc[i][0],  acc[i][1],  acc[i][2],  acc[i][3],
                               Ai[0], Ai[1], Ai[2], Ai[3], B0[0], B0[1]);
                mma_bf16_16816(acc[i][4],  acc[i][5],  acc[i][6],  acc[i][7],
                               Ai[0], Ai[1], Ai[2], Ai[3], B0[2], B0[3]);
                mma_bf16_16816(acc[i][8],  acc[i][9],  acc[i][10], acc[i][11],
                               Ai[0], Ai[1], Ai[2], Ai[3], B1[0], B1[1]);
                mma_bf16_16816(acc[i][12], acc[i][13], acc[i][14], acc[i][15],
                               Ai[0], Ai[1], Ai[2], Ai[3], B1[2], B1[3]);
            }
        }
        __syncthreads();
    }

    // epilogue: merge split-K partials
    float* Gp = g_G[pair][b];
    int grp = lane >> 2, tg = lane & 3;
    #pragma unroll
    for (int i = 0; i < 4; i++) {
        #pragma unroll
        for (int j2 = 0; j2 < 4; j2++) {
            int m = wm + 16 * i + grp;
            int d = wn + 8 * j2 + tg * 2;
            atomicAdd(&Gp[m * CC + d],           acc[i][j2 * 4 + 0]);
            atomicAdd(&Gp[m * CC + d + 1],       acc[i][j2 * 4 + 1]);
            atomicAdd(&Gp[(m + 8) * CC + d],     acc[i][j2 * 4 + 2]);
            atomicAdd(&Gp[(m + 8) * CC + d + 1], acc[i][j2 * 4 + 3]);
        }
    }
    atomicAdd(&g_n2[pair][0][b][lc],     sqx.x);
    atomicAdd(&g_n2[pair][0][b][lc + 1], sqx.y);
    atomicAdd(&g_n2[pair][0][b][lc + 2], sqx.z);
    atomicAdd(&g_n2[pair][0][b][lc + 3], sqx.w);
    atomicAdd(&g_n2[pair][1][b][lc],     sqs.x);
    atomicAdd(&g_n2[pair][1][b][lc + 1], sqs.y);
    atomicAdd(&g_n2[pair][1][b][lc + 2], sqs.z);
    atomicAdd(&g_n2[pair][1][b][lc + 3], sqs.w);
}

// reconstruction MSE sums (float4 vectorized, both pairs)
__global__ void k_recon(const float* __restrict__ r_hf, const float* __restrict__ hf,
                        const float* __restrict__ r_lf, const float* __restrict__ lf) {
    int pair = blockIdx.y;
    const float4* r = (const float4*)(pair ? r_lf : r_hf);
    const float4* o = (const float4*)(pair ? lf   : hf);
    float local = 0.f;
    int stride = gridDim.x * blockDim.x;
    for (int i = blockIdx.x * blockDim.x + threadIdx.x; i < BNC/4; i += stride) {
        float4 a = r[i], bq = o[i];
        float dx = a.x - bq.x, dy = a.y - bq.y, dz = a.z - bq.z, dw = a.w - bq.w;
        local += dx*dx + dy*dy + dz*dz + dw*dw;
    }
    block_add((double)local, &g_acc[3 + pair]);
}

// stable descending argsort rank (count-based) + positives count
__global__ void k_rank(const float* __restrict__ gt) {
    __shared__ float row[NN];
    int batch = blockIdx.y;
    const float* gr = gt + batch * NN;
    for (int j = threadIdx.x; j < NN; j += 128) row[j] = gr[j];
    __syncthreads();

    int i = blockIdx.x * 128 + threadIdx.x;
    float xi = row[i];
    int cgt = 0, ceq = 0;
    for (int j = 0; j < NN; j += 4) {
        float4 v = *(const float4*)&row[j];
        cgt += (v.x > xi) + (v.y > xi) + (v.z > xi) + (v.w > xi);
        ceq += (v.x == xi && j     < i);
        ceq += (v.y == xi && j + 1 < i);
        ceq += (v.z == xi && j + 2 < i);
        ceq += (v.w == xi && j + 3 < i);
    }
    g_ord[batch][cgt + ceq] = i;

    int pos = (xi > 0.f) ? 1 : 0;
    #pragma unroll
    for (int o = 16; o; o >>= 1) pos += __shfl_down_sync(0xffffffffu, pos, o);
    __shared__ int ws[4];
    if ((threadIdx.x & 31) == 0) ws[threadIdx.x >> 5] = pos;
    __syncthreads();
    if (threadIdx.x == 0) atomicAdd(&g_cnt[batch], ws[0] + ws[1] + ws[2] + ws[3]);
}

// masked cosine-embedding sum over sorted pairs (one warp per sorted position)
__global__ void k_sepcos(const float* __restrict__ sep) {
    int w = threadIdx.x >> 5, lane = threadIdx.x & 31;
    int p = blockIdx.x * 8 + w;
    int i0 = g_ord[0][p], i1 = g_ord[1][p];
    const float4* r0 = (const float4*)(sep + (size_t)i0 * CC);
    const float4* r1 = (const float4*)(sep + (size_t)NC + (size_t)i1 * CC);
    float4 a = r0[lane], b = r1[lane];
    float dot = a.x*b.x + a.y*b.y + a.z*b.z + a.w*b.w;
    float nx  = a.x*a.x + a.y*a.y + a.z*a.z + a.w*a.w;
    float ny  = b.x*b.x + b.y*b.y + b.z*b.z + b.w*b.w;
    dot = wredf(dot); nx = wredf(nx); ny = wredf(ny);

    __shared__ double part[8];
    if (lane == 0) {
        int s0 = g_cnt[0]; if (s0 == 0) s0 = NN;
        int s1 = g_cnt[1]; if (s1 == 0) s1 = NN;
        int index = min(s0, s1);
        float cs = dot / (fmaxf(sqrtf(nx), 1e-8f) * fmaxf(sqrtf(ny), 1e-8f));
        part[w] = (p < index) ? (double)(1.f - cs) : 0.0;
    }
    __syncthreads();
    if (threadIdx.x == 0) {
        double s = 0;
        #pragma unroll
        for (int k = 0; k < 8; k++) s += part[k];
        atomicAdd(&g_acc[1], s);
    }
}

// pearson over first 16 rows of flattened [B*N, C]
__global__ void k_pear(const float* __restrict__ x, const float* __restrict__ y) {
    int w = threadIdx.x >> 5, lane = threadIdx.x & 31;
    const float4* xr = (const float4*)(x + w * CC);
    const float4* yr = (const float4*)(y + w * CC);
    float4 a = xr[lane], b = yr[lane];
    float sx  = a.x + a.y + a.z + a.w;
    float sy  = b.x + b.y + b.z + b.w;
    float sxx = a.x*a.x + a.y*a.y + a.z*a.z + a.w*a.w;
    float syy = b.x*b.x + b.y*b.y + b.z*b.z + b.w*b.w;
    float sxy = a.x*b.x + a.y*b.y + a.z*b.z + a.w*b.w;
    sx = wredf(sx); sy = wredf(sy); sxx = wredf(sxx); syy = wredf(syy); sxy = wredf(sxy);
    if (lane == 0) {
        double n = 128.0;
        double num = (double)sxy - (double)sx * (double)sy / n;
        double d2  = ((double)sxx - (double)sx * (double)sx / n) *
                     ((double)syy - (double)sy * (double)sy / n);
        double den = sqrt(d2);
        double r   = (den == 0.0) ? 0.0 : num / den;
        atomicAdd(&g_acc[0], 1.0 - r);
    }
}

// sum of squared normalized correlations over both pairs
__global__ void k_cost() {
    int idx  = blockIdx.x * 256 + threadIdx.x;
    int pair = idx >> 18;
    int rem  = idx & (BB*CC*CC - 1);
    int b    = rem >> 14;
    int cd   = rem & (CC*CC - 1);
    int c    = cd >> 7;
    int d    = cd & (CC - 1);
    float g  = g_G[pair][b][cd];
    float nx = fmaxf(sqrtf(g_n2[pair][0][b][c]), 1e-12f);
    float ns = fmaxf(sqrtf(g_n2[pair][1][b][d]), 1e-12f);
    float v  = g / (nx * ns);
    block_add((double)(v * v), &g_acc[2]);
}

__global__ void k_final(float* __restrict__ out) {
    double sim   = g_acc[0] / 16.0;
    double cost  = g_acc[2] / (double)(BB * CC * CC);
    double recon = (g_acc[3] + g_acc[4]) / (double)BNC;
    int s0 = g_cnt[0]; if (s0 == 0) s0 = NN;
    int s1 = g_cnt[1]; if (s1 == 0) s1 = NN;
    int index = min(s0, s1);
    double gnn = g_acc[1] / (double)index;
    out[0] = (float)(2.0 * sim + 1.0 * cost + 0.05 * recon + gnn);
}

// ---------------- launch ----------------------------------------------------
extern "C" void kernel_launch(void* const* d_in, const int* in_sizes, int n_in,
                              void* d_out, int out_size) {
    const float* hf_f = (const float*)d_in[0];
    const float* lf_f = (const float*)d_in[1];
    const float* hf_s = (const float*)d_in[2];
    const float* lf_s = (const float*)d_in[3];
    const float* hf_p = (const float*)d_in[4];
    const float* lf_p = (const float*)d_in[5];
    const float* r_hf = (const float*)d_in[6];
    const float* r_lf = (const float*)d_in[7];
    const float* sep  = (const float*)d_in[8];
    /* d_in[9] = noi_node: contributes exactly zero (diff_loss on batch-of-1) */
    const float* gt   = (const float*)d_in[10];
    float* out = (float*)d_out;

    k_init  <<<2080, 256>>>();
    k_mean  <<<dim3(NC/4/256, 4), 256>>>(hf_s, hf_p, lf_s, lf_p);
    k_rank  <<<dim3(64, 2), 128>>>(gt);
    k_recon <<<dim3(1024, 2), 256>>>(r_hf, hf_f, r_lf, lf_f);
    k_gemm  <<<dim3(8, 16, 2), 256>>>(hf_s, hf_p, lf_s, lf_p);
    k_sepcos<<<1024, 256>>>(sep);
    k_pear  <<<1, 512>>>(hf_s, lf_s);
    k_cost  <<<2048, 256>>>();
    k_final <<<1, 1>>>(out);
}